// round 3
// baseline (speedup 1.0000x reference)
#include <cuda_runtime.h>
#include <cuda_bf16.h>
#include <math.h>

#define BATCH   4096
#define D1      200
#define NREL    500
#define M1      288      // OC*FW
#define OC      32
#define FW      9
#define WOUT    392
#define WIN     400
#define FCLEN   12544
#define EPSBN   1e-5f
#define NSPLIT  8
#define ILEN    50       // WIN / NSPLIT
#define FBLK    49       // FCLEN / 256

// gemm1 geometry: Krel[500x288] = R[500x200] @ fc1w[288x200]^T
#define G1_ROWB 16       // ceil(500/32)
#define G1_COLB 5        // ceil(288/64)
// gemm2 geometry: q[500x400] = Krel[500x288] @ Vmat[288x400]
#define G2_ROWB 16
#define G2_COLB 7

// ---------------- device scratch ----------------
__device__ float g_vp[NSPLIT * FCLEN];   // v partial sums
__device__ float g_Krel[NREL * M1];
__device__ float g_Vmat[M1 * WIN];
__device__ float g_q[NREL * WIN];
__device__ float g_c1[OC];
__device__ float g_scal0;

// ======== L1: k1 v-partials + scal0 + gemm1 (independent, fused) ========
__global__ void L1_fused(const float* __restrict__ fcw,
                         const float* __restrict__ bn2g, const float* __restrict__ bn2b,
                         const float* __restrict__ bn2m, const float* __restrict__ bn2v,
                         const float* __restrict__ fc2w, const float* __restrict__ fc2b,
                         const float* __restrict__ fcb,
                         const float* __restrict__ R, const float* __restrict__ fc1w,
                         const float* __restrict__ fc1b) {
    __shared__ float smem[8 * 68 + 8 * 36];   // gemm1: Bs[8][68] + As[8][36]
    int tid = threadIdx.x;
    int bid = blockIdx.x;

    if (bid < NSPLIT * FBLK) {                // ---- k1: v partials ----
        float* sa = smem;                      // [ILEN]
        int isp = bid / FBLK, fb = bid % FBLK;
        if (tid < ILEN) {
            int i = isp * ILEN + tid;
            float s2 = bn2g[i] * rsqrtf(bn2v[i] + EPSBN);
            sa[tid] = s2 * fc2w[i];
        }
        __syncthreads();
        int f = fb * 256 + tid;
        const float* __restrict__ p = fcw + (size_t)isp * ILEN * FCLEN + f;
        float acc = 0.f;
#pragma unroll
        for (int ii = 0; ii < ILEN; ii++)
            acc = fmaf(sa[ii], p[(size_t)ii * FCLEN], acc);
        g_vp[isp * FCLEN + f] = acc;
        return;
    }
    if (bid == NSPLIT * FBLK) {               // ---- scal0 ----
        float* red = smem;
        float t = 0.f;
        for (int i = tid; i < WIN; i += 256) {
            float s2 = bn2g[i] * rsqrtf(bn2v[i] + EPSBN);
            float a  = s2 * fc2w[i];
            t += (bn2b[i] - bn2m[i] * s2) * fc2w[i] + a * fcb[i];
        }
        red[tid] = t;
        __syncthreads();
        for (int s = 128; s; s >>= 1) { if (tid < s) red[tid] += red[tid + s]; __syncthreads(); }
        if (tid == 0) g_scal0 = red[0] + fc2b[0];
        return;
    }
    // ---- gemm1: 32x64 tile, 256 thr, 2x4 thread tile, KC=8 ----
    int gb = bid - (NSPLIT * FBLK + 1);
    int row0 = (gb % G1_ROWB) * 32;
    int col0 = (gb / G1_ROWB) * 64;
    float* Bs = smem;                         // [8][68]
    float* As = smem + 8 * 68;                // [8][36]
    int tx = tid & 15, ty = tid >> 4;         // tx: 4-col group, ty: 2-row group
    float acc[2][4] = {};
    for (int k0 = 0; k0 < 200; k0 += 8) {
        {   // As: 256 elems, 1/thread
            int m = tid >> 3, kk = tid & 7;
            int gm = row0 + m;
            As[kk * 36 + m] = (gm < NREL) ? R[gm * 200 + k0 + kk] : 0.f;
        }
#pragma unroll
        for (int l = 0; l < 2; l++) {         // Bs: 512 elems (transpose load)
            int e = l * 256 + tid;
            int n = e >> 3, kk = e & 7;
            int gn = col0 + n;
            Bs[kk * 68 + n] = (gn < M1) ? fc1w[gn * 200 + k0 + kk] : 0.f;
        }
        __syncthreads();
#pragma unroll
        for (int kk = 0; kk < 8; kk++) {
            float a0 = As[kk * 36 + ty * 2];
            float a1 = As[kk * 36 + ty * 2 + 1];
            float4 b4 = *(const float4*)&Bs[kk * 68 + tx * 4];
            acc[0][0] = fmaf(a0, b4.x, acc[0][0]); acc[0][1] = fmaf(a0, b4.y, acc[0][1]);
            acc[0][2] = fmaf(a0, b4.z, acc[0][2]); acc[0][3] = fmaf(a0, b4.w, acc[0][3]);
            acc[1][0] = fmaf(a1, b4.x, acc[1][0]); acc[1][1] = fmaf(a1, b4.y, acc[1][1]);
            acc[1][2] = fmaf(a1, b4.z, acc[1][2]); acc[1][3] = fmaf(a1, b4.w, acc[1][3]);
        }
        __syncthreads();
    }
#pragma unroll
    for (int mi = 0; mi < 2; mi++) {
        int gm = row0 + ty * 2 + mi;
        if (gm < NREL) {
#pragma unroll
            for (int ni = 0; ni < 4; ni++) {
                int gn = col0 + tx * 4 + ni;
                if (gn < M1) g_Krel[gm * M1 + gn] = acc[mi][ni] + fc1b[gn];
            }
        }
    }
}

// ======== L2: kv_build — fold partials, scale, shift-replicate ==========
__global__ void kv_build(const float* __restrict__ bn1g, const float* __restrict__ bn1b,
                         const float* __restrict__ bn1m, const float* __restrict__ bn1v) {
    __shared__ float sv[WOUT];
    __shared__ float red[256];
    int o = blockIdx.x, tid = threadIdx.x;
    float inv1 = bn1g[o] * rsqrtf(bn1v[o] + EPSBN);
    float vsum = 0.f;
    for (int w = tid; w < WOUT; w += 256) {
        float s = 0.f;
#pragma unroll
        for (int sp = 0; sp < NSPLIT; sp++) s += g_vp[sp * FCLEN + o * WOUT + w];
        sv[w] = s * inv1;
        vsum += s;
    }
    red[tid] = vsum;
    __syncthreads();
    for (int s = 128; s; s >>= 1) { if (tid < s) red[tid] += red[tid + s]; __syncthreads(); }
    if (tid == 0) g_c1[o] = (bn1b[o] - bn1m[o] * inv1) * red[0];
    for (int idx = tid; idx < FW * WIN; idx += 256) {
        int j = idx / WIN, t = idx - j * WIN;
        int w = t - j;
        g_Vmat[(o * FW + j) * WIN + t] = ((unsigned)w < (unsigned)WOUT) ? sv[w] : 0.f;
    }
}

// ======== L3: gemm2 — q = Krel @ Vmat, 32x64 tile, 256 thr ==============
__global__ void gemm2_q() {
    __shared__ float Bs[16 * 68];
    __shared__ float As[16 * 36];
    int tid = threadIdx.x;
    int row0 = blockIdx.x * 32, col0 = blockIdx.y * 64;
    int tx = tid & 15, ty = tid >> 4;
    float acc[2][4] = {};
    for (int k0 = 0; k0 < M1; k0 += 16) {
#pragma unroll
        for (int l = 0; l < 2; l++) {          // As: 512 elems
            int e = l * 256 + tid;
            int m = e >> 4, kk = e & 15;
            int gm = row0 + m;
            As[kk * 36 + m] = (gm < NREL) ? g_Krel[gm * M1 + k0 + kk] : 0.f;
        }
#pragma unroll
        for (int l = 0; l < 4; l++) {          // Bs: 1024 elems, coalesced
            int e = l * 256 + tid;
            int kk = e >> 6, n = e & 63;
            int gn = col0 + n;
            Bs[kk * 68 + n] = (gn < WIN) ? g_Vmat[(k0 + kk) * WIN + gn] : 0.f;
        }
        __syncthreads();
#pragma unroll
        for (int kk = 0; kk < 16; kk++) {
            float a0 = As[kk * 36 + ty * 2];
            float a1 = As[kk * 36 + ty * 2 + 1];
            float4 b4 = *(const float4*)&Bs[kk * 68 + tx * 4];
            acc[0][0] = fmaf(a0, b4.x, acc[0][0]); acc[0][1] = fmaf(a0, b4.y, acc[0][1]);
            acc[0][2] = fmaf(a0, b4.z, acc[0][2]); acc[0][3] = fmaf(a0, b4.w, acc[0][3]);
            acc[1][0] = fmaf(a1, b4.x, acc[1][0]); acc[1][1] = fmaf(a1, b4.y, acc[1][1]);
            acc[1][2] = fmaf(a1, b4.z, acc[1][2]); acc[1][3] = fmaf(a1, b4.w, acc[1][3]);
        }
        __syncthreads();
    }
#pragma unroll
    for (int mi = 0; mi < 2; mi++) {
        int gm = row0 + ty * 2 + mi;
        if (gm < NREL) {
#pragma unroll
            for (int ni = 0; ni < 4; ni++) {
                int gn = col0 + tx * 4 + ni;
                if (gn < WIN) g_q[gm * WIN + gn] = acc[mi][ni];
            }
        }
    }
}

// ======== L4: main — gather + folded 400-dot + tanh =====================
__global__ void k4_main(const int* __restrict__ e1i, const int* __restrict__ ri,
                        const int* __restrict__ e2i, const float* __restrict__ Et,
                        const float* __restrict__ bn0g, const float* __restrict__ bn0b,
                        const float* __restrict__ bn0m, const float* __restrict__ bn0v,
                        const float* __restrict__ bias, float* __restrict__ out) {
    int warp = threadIdx.x >> 5, lane = threadIdx.x & 31;
    int b = blockIdx.x * 8 + warp;
    float s0 = bn0g[0] * rsqrtf(bn0v[0] + EPSBN);
    float c0 = bn0b[0] - bn0m[0] * s0;
    int e1 = e1i[b], e2 = e2i[b], r = ri[b];
    const float4* __restrict__ Q  = (const float4*)(g_q + r * WIN);
    const float4* __restrict__ E1 = (const float4*)(Et + (size_t)e1 * D1);
    const float4* __restrict__ E2 = (const float4*)(Et + (size_t)e2 * D1);
    float acc = g_c1[lane];
    for (int u = lane; u < 100; u += 32) {
        float4 ev = (u < 50) ? E1[u] : E2[u - 50];
        float4 qv = Q[u];
        acc = fmaf(fmaf(s0, ev.x, c0), qv.x, acc);
        acc = fmaf(fmaf(s0, ev.y, c0), qv.y, acc);
        acc = fmaf(fmaf(s0, ev.z, c0), qv.z, acc);
        acc = fmaf(fmaf(s0, ev.w, c0), qv.w, acc);
    }
    for (int o = 16; o; o >>= 1) acc += __shfl_down_sync(0xffffffffu, acc, o);
    if (lane == 0)
        out[b] = tanhf(acc + g_scal0) + bias[0];
}

// ---------------- launch ------------------------------------------------
extern "C" void kernel_launch(void* const* d_in, const int* in_sizes, int n_in,
                              void* d_out, int out_size) {
    const int*   e1_idx  = (const int*)  d_in[0];
    const int*   r_idx   = (const int*)  d_in[1];
    const int*   e2_idx  = (const int*)  d_in[2];
    const float* E_table = (const float*)d_in[3];
    const float* R_table = (const float*)d_in[4];
    const float* bn0g    = (const float*)d_in[5];
    const float* bn0b    = (const float*)d_in[6];
    const float* bn0m    = (const float*)d_in[7];
    const float* bn0v    = (const float*)d_in[8];
    const float* fc1w    = (const float*)d_in[9];
    const float* fc1b    = (const float*)d_in[10];
    const float* bn1g    = (const float*)d_in[11];
    const float* bn1b    = (const float*)d_in[12];
    const float* bn1m    = (const float*)d_in[13];
    const float* bn1v    = (const float*)d_in[14];
    const float* fcw     = (const float*)d_in[15];
    const float* fcb     = (const float*)d_in[16];
    const float* bn2g    = (const float*)d_in[17];
    const float* bn2b    = (const float*)d_in[18];
    const float* bn2m    = (const float*)d_in[19];
    const float* bn2v    = (const float*)d_in[20];
    const float* fc2w    = (const float*)d_in[21];
    const float* fc2b    = (const float*)d_in[22];
    const float* bias    = (const float*)d_in[23];
    float* out = (float*)d_out;

    int l1_blocks = NSPLIT * FBLK + 1 + G1_ROWB * G1_COLB;   // 393 + 80
    L1_fused<<<l1_blocks, 256>>>(fcw, bn2g, bn2b, bn2m, bn2v, fc2w, fc2b, fcb,
                                 R_table, fc1w, fc1b);
    kv_build<<<OC, 256>>>(bn1g, bn1b, bn1m, bn1v);
    gemm2_q<<<dim3(G2_ROWB, G2_COLB), 256>>>();
    k4_main<<<BATCH / 8, 256>>>(e1_idx, r_idx, e2_idx, E_table,
                                bn0g, bn0b, bn0m, bn0v, bias, out);
}

// round 4
// speedup vs baseline: 1.0478x; 1.0478x over previous
#include <cuda_runtime.h>
#include <cuda_bf16.h>
#include <math.h>

#define BATCH   4096
#define D1      200
#define NREL    500
#define M1      288      // OC*FW
#define OC      32
#define FW      9
#define WOUT    392
#define WIN     400
#define FCLEN   12544
#define EPSBN   1e-5f
#define NSPLIT  8
#define ILEN    50       // WIN / NSPLIT
#define FBLK    49       // FCLEN / 256

#define G1_ROWB 16
#define G1_COLB 5
#define G2_ROWB 16
#define G2_COLB 7

// ---------------- device scratch ----------------
__device__ float g_vp[NSPLIT * FCLEN];
__device__ float g_Krel[NREL * M1];
__device__ float g_Vmat[M1 * WIN];
__device__ float g_q[NREL * WIN];
__device__ float g_c1[OC];
__device__ float g_scal0;

// ======== K1: v partials (8-way i-split), standalone (R2-proven) ========
__global__ void __launch_bounds__(256) k1_v(
        const float* __restrict__ fcw,
        const float* __restrict__ bn2g, const float* __restrict__ bn2v,
        const float* __restrict__ fc2w) {
    __shared__ float sa[ILEN];
    int tid = threadIdx.x;
    int isp = blockIdx.x / FBLK, fb = blockIdx.x % FBLK;
    if (tid < ILEN) {
        int i = isp * ILEN + tid;
        float s2 = bn2g[i] * rsqrtf(bn2v[i] + EPSBN);
        sa[tid] = s2 * fc2w[i];
    }
    __syncthreads();
    int f = fb * 256 + tid;
    const float* __restrict__ p = fcw + (size_t)isp * ILEN * FCLEN + f;
    float acc = 0.f;
#pragma unroll
    for (int ii = 0; ii < ILEN; ii++)
        acc = fmaf(sa[ii], p[(size_t)ii * FCLEN], acc);
    g_vp[isp * FCLEN + f] = acc;
}

// ======== GEMM1: Krel = R @ fc1w^T + b, 32x64 tile, 256 thr =============
__global__ void __launch_bounds__(256) gemm1_krel(
        const float* __restrict__ R, const float* __restrict__ fc1w,
        const float* __restrict__ fc1b) {
    __shared__ float Bs[8 * 68];
    __shared__ float As[8 * 36];
    int tid = threadIdx.x;
    int row0 = blockIdx.x * 32, col0 = blockIdx.y * 64;
    int tx = tid & 15, ty = tid >> 4;
    float acc[2][4] = {};
    for (int k0 = 0; k0 < 200; k0 += 8) {
        {
            int m = tid >> 3, kk = tid & 7;
            int gm = row0 + m;
            As[kk * 36 + m] = (gm < NREL) ? R[gm * 200 + k0 + kk] : 0.f;
        }
#pragma unroll
        for (int l = 0; l < 2; l++) {
            int e = l * 256 + tid;
            int n = e >> 3, kk = e & 7;
            int gn = col0 + n;
            Bs[kk * 68 + n] = (gn < M1) ? fc1w[gn * 200 + k0 + kk] : 0.f;
        }
        __syncthreads();
#pragma unroll
        for (int kk = 0; kk < 8; kk++) {
            float a0 = As[kk * 36 + ty * 2];
            float a1 = As[kk * 36 + ty * 2 + 1];
            float4 b4 = *(const float4*)&Bs[kk * 68 + tx * 4];
            acc[0][0] = fmaf(a0, b4.x, acc[0][0]); acc[0][1] = fmaf(a0, b4.y, acc[0][1]);
            acc[0][2] = fmaf(a0, b4.z, acc[0][2]); acc[0][3] = fmaf(a0, b4.w, acc[0][3]);
            acc[1][0] = fmaf(a1, b4.x, acc[1][0]); acc[1][1] = fmaf(a1, b4.y, acc[1][1]);
            acc[1][2] = fmaf(a1, b4.z, acc[1][2]); acc[1][3] = fmaf(a1, b4.w, acc[1][3]);
        }
        __syncthreads();
    }
#pragma unroll
    for (int mi = 0; mi < 2; mi++) {
        int gm = row0 + ty * 2 + mi;
        if (gm < NREL) {
#pragma unroll
            for (int ni = 0; ni < 4; ni++) {
                int gn = col0 + tx * 4 + ni;
                if (gn < M1) g_Krel[gm * M1 + gn] = acc[mi][ni] + fc1b[gn];
            }
        }
    }
}

// ======== KV: fold partials, scale, shift-replicate (+ scal0 block) =====
__global__ void __launch_bounds__(256) kv_build(
        const float* __restrict__ bn1g, const float* __restrict__ bn1b,
        const float* __restrict__ bn1m, const float* __restrict__ bn1v,
        const float* __restrict__ bn2g, const float* __restrict__ bn2b,
        const float* __restrict__ bn2m, const float* __restrict__ bn2v,
        const float* __restrict__ fc2w, const float* __restrict__ fc2b,
        const float* __restrict__ fcb) {
    __shared__ float sv[WOUT];
    __shared__ float red[256];
    int tid = threadIdx.x;
    if (blockIdx.x == OC) {                // scal0
        float t = 0.f;
        for (int i = tid; i < WIN; i += 256) {
            float s2 = bn2g[i] * rsqrtf(bn2v[i] + EPSBN);
            float a  = s2 * fc2w[i];
            t += (bn2b[i] - bn2m[i] * s2) * fc2w[i] + a * fcb[i];
        }
        red[tid] = t;
        __syncthreads();
        for (int s = 128; s; s >>= 1) { if (tid < s) red[tid] += red[tid + s]; __syncthreads(); }
        if (tid == 0) g_scal0 = red[0] + fc2b[0];
        return;
    }
    int o = blockIdx.x;
    float inv1 = bn1g[o] * rsqrtf(bn1v[o] + EPSBN);
    float vsum = 0.f;
    for (int w = tid; w < WOUT; w += 256) {
        float s = 0.f;
#pragma unroll
        for (int sp = 0; sp < NSPLIT; sp++) s += g_vp[sp * FCLEN + o * WOUT + w];
        sv[w] = s * inv1;
        vsum += s;
    }
    red[tid] = vsum;
    __syncthreads();
    for (int s = 128; s; s >>= 1) { if (tid < s) red[tid] += red[tid + s]; __syncthreads(); }
    if (tid == 0) g_c1[o] = (bn1b[o] - bn1m[o] * inv1) * red[0];
    __syncthreads();
    for (int idx = tid; idx < FW * WIN; idx += 256) {
        int j = idx / WIN, t = idx - j * WIN;
        int w = t - j;
        g_Vmat[(o * FW + j) * WIN + t] = ((unsigned)w < (unsigned)WOUT) ? sv[w] : 0.f;
    }
}

// ======== GEMM2: q = Krel @ Vmat, 32x64 tile, 256 thr ===================
__global__ void __launch_bounds__(256) gemm2_q() {
    __shared__ float Bs[16 * 68];
    __shared__ float As[16 * 36];
    int tid = threadIdx.x;
    int row0 = blockIdx.x * 32, col0 = blockIdx.y * 64;
    int tx = tid & 15, ty = tid >> 4;
    float acc[2][4] = {};
    for (int k0 = 0; k0 < M1; k0 += 16) {
#pragma unroll
        for (int l = 0; l < 2; l++) {
            int e = l * 256 + tid;
            int m = e >> 4, kk = e & 15;
            int gm = row0 + m;
            As[kk * 36 + m] = (gm < NREL) ? g_Krel[gm * M1 + k0 + kk] : 0.f;
        }
#pragma unroll
        for (int l = 0; l < 4; l++) {
            int e = l * 256 + tid;
            int kk = e >> 6, n = e & 63;
            int gn = col0 + n;
            Bs[kk * 68 + n] = (gn < WIN) ? g_Vmat[(k0 + kk) * WIN + gn] : 0.f;
        }
        __syncthreads();
#pragma unroll
        for (int kk = 0; kk < 16; kk++) {
            float a0 = As[kk * 36 + ty * 2];
            float a1 = As[kk * 36 + ty * 2 + 1];
            float4 b4 = *(const float4*)&Bs[kk * 68 + tx * 4];
            acc[0][0] = fmaf(a0, b4.x, acc[0][0]); acc[0][1] = fmaf(a0, b4.y, acc[0][1]);
            acc[0][2] = fmaf(a0, b4.z, acc[0][2]); acc[0][3] = fmaf(a0, b4.w, acc[0][3]);
            acc[1][0] = fmaf(a1, b4.x, acc[1][0]); acc[1][1] = fmaf(a1, b4.y, acc[1][1]);
            acc[1][2] = fmaf(a1, b4.z, acc[1][2]); acc[1][3] = fmaf(a1, b4.w, acc[1][3]);
        }
        __syncthreads();
    }
#pragma unroll
    for (int mi = 0; mi < 2; mi++) {
        int gm = row0 + ty * 2 + mi;
        if (gm < NREL) {
#pragma unroll
            for (int ni = 0; ni < 4; ni++) {
                int gn = col0 + tx * 4 + ni;
                if (gn < WIN) g_q[gm * WIN + gn] = acc[mi][ni];
            }
        }
    }
}

// ======== K4: 2 warps per example (double warp-parallelism) =============
__global__ void __launch_bounds__(256) k4_main(
        const int* __restrict__ e1i, const int* __restrict__ ri,
        const int* __restrict__ e2i, const float* __restrict__ Et,
        const float* __restrict__ bn0g, const float* __restrict__ bn0b,
        const float* __restrict__ bn0m, const float* __restrict__ bn0v,
        const float* __restrict__ bias, float* __restrict__ out) {
    __shared__ float part[8];
    int tid = threadIdx.x;
    int lane = tid & 31;
    int half = (tid >> 5) & 1;             // 0: E1·q_lo, 1: E2·q_hi
    int k = tid >> 6;                      // 0..3 local example
    int b = blockIdx.x * 4 + k;
    float s0 = bn0g[0] * rsqrtf(bn0v[0] + EPSBN);
    float c0 = bn0b[0] - bn0m[0] * s0;
    int r  = ri[b];
    int e  = half ? e2i[b] : e1i[b];
    const float4* __restrict__ E = (const float4*)(Et + (size_t)e * D1);     // 50 f4
    const float4* __restrict__ Q = (const float4*)(g_q + r * WIN) + half * 50;
    float acc = half ? 0.f : g_c1[lane];
    // u = lane and lane+32 (lane+32 valid for lane<18)
    {
        float4 ev = E[lane], qv = Q[lane];
        acc = fmaf(fmaf(s0, ev.x, c0), qv.x, acc);
        acc = fmaf(fmaf(s0, ev.y, c0), qv.y, acc);
        acc = fmaf(fmaf(s0, ev.z, c0), qv.z, acc);
        acc = fmaf(fmaf(s0, ev.w, c0), qv.w, acc);
    }
    if (lane < 18) {
        float4 ev = E[lane + 32], qv = Q[lane + 32];
        acc = fmaf(fmaf(s0, ev.x, c0), qv.x, acc);
        acc = fmaf(fmaf(s0, ev.y, c0), qv.y, acc);
        acc = fmaf(fmaf(s0, ev.z, c0), qv.z, acc);
        acc = fmaf(fmaf(s0, ev.w, c0), qv.w, acc);
    }
    for (int o = 16; o; o >>= 1) acc += __shfl_down_sync(0xffffffffu, acc, o);
    if (lane == 0) part[tid >> 5] = acc;
    __syncthreads();
    if ((tid & 63) == 0) {
        int w = tid >> 5;
        float z = part[w] + part[w + 1] + g_scal0;
        out[b] = tanhf(z) + bias[0];
    }
}

// ---------------- launch ------------------------------------------------
extern "C" void kernel_launch(void* const* d_in, const int* in_sizes, int n_in,
                              void* d_out, int out_size) {
    const int*   e1_idx  = (const int*)  d_in[0];
    const int*   r_idx   = (const int*)  d_in[1];
    const int*   e2_idx  = (const int*)  d_in[2];
    const float* E_table = (const float*)d_in[3];
    const float* R_table = (const float*)d_in[4];
    const float* bn0g    = (const float*)d_in[5];
    const float* bn0b    = (const float*)d_in[6];
    const float* bn0m    = (const float*)d_in[7];
    const float* bn0v    = (const float*)d_in[8];
    const float* fc1w    = (const float*)d_in[9];
    const float* fc1b    = (const float*)d_in[10];
    const float* bn1g    = (const float*)d_in[11];
    const float* bn1b    = (const float*)d_in[12];
    const float* bn1m    = (const float*)d_in[13];
    const float* bn1v    = (const float*)d_in[14];
    const float* fcw     = (const float*)d_in[15];
    const float* fcb     = (const float*)d_in[16];
    const float* bn2g    = (const float*)d_in[17];
    const float* bn2b    = (const float*)d_in[18];
    const float* bn2m    = (const float*)d_in[19];
    const float* bn2v    = (const float*)d_in[20];
    const float* fc2w    = (const float*)d_in[21];
    const float* fc2b    = (const float*)d_in[22];
    const float* bias    = (const float*)d_in[23];
    float* out = (float*)d_out;

    k1_v<<<NSPLIT * FBLK, 256>>>(fcw, bn2g, bn2v, fc2w);
    gemm1_krel<<<dim3(G1_ROWB, G1_COLB), 256>>>(R_table, fc1w, fc1b);
    kv_build<<<OC + 1, 256>>>(bn1g, bn1b, bn1m, bn1v,
                              bn2g, bn2b, bn2m, bn2v, fc2w, fc2b, fcb);
    gemm2_q<<<dim3(G2_ROWB, G2_COLB), 256>>>();
    k4_main<<<BATCH / 4, 256>>>(e1_idx, r_idx, e2_idx, E_table,
                                bn0g, bn0b, bn0m, bn0v, bias, out);
}

// round 5
// speedup vs baseline: 1.0486x; 1.0008x over previous
#include <cuda_runtime.h>
#include <cuda_bf16.h>
#include <math.h>

#define BATCH   4096
#define D1      200
#define NREL    500
#define NRELP   512      // padded rel count for KrelT
#define M1      288      // OC*FW
#define OC      32
#define FW      9
#define WOUT    392
#define WIN     400
#define VPAD    448      // padded Vmat row stride
#define FCLEN   12544
#define EPSBN   1e-5f
#define NSPLIT  8
#define ILEN    50
#define FBLK    49

#define G1_ROWB 16
#define G1_COLB 5

// gemm2 v3 geometry
#define G2_TM   64
#define G2_TN   64
#define G2_KC   8
#define KSPL    2        // 288/2 = 144 per split, 144/8 = 18 steps
#define KHALF   144
#define KSTEPS  18

// ---------------- device scratch ----------------
__device__ float g_vp[NSPLIT * FCLEN];
__device__ float g_KrelT[M1 * NRELP];      // K-major: [k][rel], pad rows zero
__device__ float g_Vmat[M1 * VPAD];        // pad cols zero
__device__ float g_qp[KSPL * NREL * WIN];  // K-split partials
__device__ float g_c1[OC];
__device__ float g_scal0;

// ======== K1: v partials (8-way i-split) ================================
__global__ void __launch_bounds__(256) k1_v(
        const float* __restrict__ fcw,
        const float* __restrict__ bn2g, const float* __restrict__ bn2v,
        const float* __restrict__ fc2w) {
    __shared__ float sa[ILEN];
    int tid = threadIdx.x;
    int isp = blockIdx.x / FBLK, fb = blockIdx.x % FBLK;
    if (tid < ILEN) {
        int i = isp * ILEN + tid;
        float s2 = bn2g[i] * rsqrtf(bn2v[i] + EPSBN);
        sa[tid] = s2 * fc2w[i];
    }
    __syncthreads();
    int f = fb * 256 + tid;
    const float* __restrict__ p = fcw + (size_t)isp * ILEN * FCLEN + f;
    float acc = 0.f;
#pragma unroll
    for (int ii = 0; ii < ILEN; ii++)
        acc = fmaf(sa[ii], p[(size_t)ii * FCLEN], acc);
    g_vp[isp * FCLEN + f] = acc;
}

// ======== GEMM1: KrelT[k][rel] = (R @ fc1w^T + b)^T =====================
__global__ void __launch_bounds__(256) gemm1_krel(
        const float* __restrict__ R, const float* __restrict__ fc1w,
        const float* __restrict__ fc1b) {
    __shared__ float Bs[8 * 68];
    __shared__ float As[8 * 36];
    int tid = threadIdx.x;
    int row0 = blockIdx.x * 32, col0 = blockIdx.y * 64;
    int tx = tid & 15, ty = tid >> 4;
    float acc[2][4] = {};
    for (int k0 = 0; k0 < 200; k0 += 8) {
        {
            int m = tid >> 3, kk = tid & 7;
            int gm = row0 + m;
            As[kk * 36 + m] = (gm < NREL) ? R[gm * 200 + k0 + kk] : 0.f;
        }
#pragma unroll
        for (int l = 0; l < 2; l++) {
            int e = l * 256 + tid;
            int n = e >> 3, kk = e & 7;
            int gn = col0 + n;
            Bs[kk * 68 + n] = (gn < M1) ? fc1w[gn * 200 + k0 + kk] : 0.f;
        }
        __syncthreads();
#pragma unroll
        for (int kk = 0; kk < 8; kk++) {
            float a0 = As[kk * 36 + ty * 2];
            float a1 = As[kk * 36 + ty * 2 + 1];
            float4 b4 = *(const float4*)&Bs[kk * 68 + tx * 4];
            acc[0][0] = fmaf(a0, b4.x, acc[0][0]); acc[0][1] = fmaf(a0, b4.y, acc[0][1]);
            acc[0][2] = fmaf(a0, b4.z, acc[0][2]); acc[0][3] = fmaf(a0, b4.w, acc[0][3]);
            acc[1][0] = fmaf(a1, b4.x, acc[1][0]); acc[1][1] = fmaf(a1, b4.y, acc[1][1]);
            acc[1][2] = fmaf(a1, b4.z, acc[1][2]); acc[1][3] = fmaf(a1, b4.w, acc[1][3]);
        }
        __syncthreads();
    }
#pragma unroll
    for (int mi = 0; mi < 2; mi++) {
        int gm = row0 + ty * 2 + mi;       // rel
        if (gm < NREL) {
#pragma unroll
            for (int ni = 0; ni < 4; ni++) {
                int gn = col0 + tx * 4 + ni;   // k
                if (gn < M1) g_KrelT[gn * NRELP + gm] = acc[mi][ni] + fc1b[gn];
            }
        }
    }
}

// ======== KV: fold partials, scale, shift-replicate (+ scal0 block) =====
__global__ void __launch_bounds__(256) kv_build(
        const float* __restrict__ bn1g, const float* __restrict__ bn1b,
        const float* __restrict__ bn1m, const float* __restrict__ bn1v,
        const float* __restrict__ bn2g, const float* __restrict__ bn2b,
        const float* __restrict__ bn2m, const float* __restrict__ bn2v,
        const float* __restrict__ fc2w, const float* __restrict__ fc2b,
        const float* __restrict__ fcb) {
    __shared__ float sv[WOUT];
    __shared__ float red[256];
    int tid = threadIdx.x;
    if (blockIdx.x == OC) {                // scal0
        float t = 0.f;
        for (int i = tid; i < WIN; i += 256) {
            float s2 = bn2g[i] * rsqrtf(bn2v[i] + EPSBN);
            float a  = s2 * fc2w[i];
            t += (bn2b[i] - bn2m[i] * s2) * fc2w[i] + a * fcb[i];
        }
        red[tid] = t;
        __syncthreads();
        for (int s = 128; s; s >>= 1) { if (tid < s) red[tid] += red[tid + s]; __syncthreads(); }
        if (tid == 0) g_scal0 = red[0] + fc2b[0];
        return;
    }
    int o = blockIdx.x;
    float inv1 = bn1g[o] * rsqrtf(bn1v[o] + EPSBN);
    float vsum = 0.f;
    for (int w = tid; w < WOUT; w += 256) {
        float s = 0.f;
#pragma unroll
        for (int sp = 0; sp < NSPLIT; sp++) s += g_vp[sp * FCLEN + o * WOUT + w];
        sv[w] = s * inv1;
        vsum += s;
    }
    red[tid] = vsum;
    __syncthreads();
    for (int s = 128; s; s >>= 1) { if (tid < s) red[tid] += red[tid + s]; __syncthreads(); }
    if (tid == 0) g_c1[o] = (bn1b[o] - bn1m[o] * inv1) * red[0];
    __syncthreads();
    for (int idx = tid; idx < FW * WIN; idx += 256) {
        int j = idx / WIN, t = idx - j * WIN;
        int w = t - j;
        g_Vmat[(o * FW + j) * VPAD + t] = ((unsigned)w < (unsigned)WOUT) ? sv[w] : 0.f;
    }
}

// ======== GEMM2 v3: 64x64 tile, 128 thr, 4x8 per thread, K-split 2, =====
// ======== double-buffered smem with register prefetch ===================
__global__ void __launch_bounds__(128) gemm2_q() {
    __shared__ float As[2][G2_KC][68];     // [buf][kk][m]  (uses 0..63)
    __shared__ float Bs[2][G2_KC][68];     // [buf][kk][n]
    int tid = threadIdx.x;
    int tx = tid & 7;                      // col group (x8)
    int ty = tid >> 3;                     // row group (x4)
    int row0 = blockIdx.x * G2_TM;
    int col0 = blockIdx.y * G2_TN;
    int kb   = blockIdx.z * KHALF;
    float acc[4][8] = {};
    float ar[4], br[4];

    // preload step 0 directly into buffer 0
#pragma unroll
    for (int l = 0; l < 4; l++) {
        int e = l * 128 + tid;
        int kk = e >> 6, m = e & 63;
        As[0][kk][m] = g_KrelT[(kb + kk) * NRELP + row0 + m];
        Bs[0][kk][m] = g_Vmat[(kb + kk) * VPAD + col0 + m];
    }
    __syncthreads();

    for (int s = 0; s < KSTEPS; s++) {
        int cur = s & 1;
        if (s + 1 < KSTEPS) {              // prefetch next tile into regs
            int kn = kb + (s + 1) * G2_KC;
#pragma unroll
            for (int l = 0; l < 4; l++) {
                int e = l * 128 + tid;
                int kk = e >> 6, m = e & 63;
                ar[l] = g_KrelT[(kn + kk) * NRELP + row0 + m];
                br[l] = g_Vmat[(kn + kk) * VPAD + col0 + m];
            }
        }
#pragma unroll
        for (int kk = 0; kk < G2_KC; kk++) {
            float4 a4 = *(const float4*)&As[cur][kk][ty * 4];
            float4 b0 = *(const float4*)&Bs[cur][kk][tx * 8];
            float4 b1 = *(const float4*)&Bs[cur][kk][tx * 8 + 4];
            float av[4] = {a4.x, a4.y, a4.z, a4.w};
#pragma unroll
            for (int mi = 0; mi < 4; mi++) {
                acc[mi][0] = fmaf(av[mi], b0.x, acc[mi][0]);
                acc[mi][1] = fmaf(av[mi], b0.y, acc[mi][1]);
                acc[mi][2] = fmaf(av[mi], b0.z, acc[mi][2]);
                acc[mi][3] = fmaf(av[mi], b0.w, acc[mi][3]);
                acc[mi][4] = fmaf(av[mi], b1.x, acc[mi][4]);
                acc[mi][5] = fmaf(av[mi], b1.y, acc[mi][5]);
                acc[mi][6] = fmaf(av[mi], b1.z, acc[mi][6]);
                acc[mi][7] = fmaf(av[mi], b1.w, acc[mi][7]);
            }
        }
        if (s + 1 < KSTEPS) {
            int nxt = cur ^ 1;
#pragma unroll
            for (int l = 0; l < 4; l++) {
                int e = l * 128 + tid;
                int kk = e >> 6, m = e & 63;
                As[nxt][kk][m] = ar[l];
                Bs[nxt][kk][m] = br[l];
            }
            __syncthreads();
        }
    }
    float* qp = g_qp + (size_t)blockIdx.z * NREL * WIN;
#pragma unroll
    for (int mi = 0; mi < 4; mi++) {
        int gm = row0 + ty * 4 + mi;
        if (gm < NREL) {
#pragma unroll
            for (int half = 0; half < 2; half++) {
                int gn = col0 + tx * 8 + half * 4;
                if (gn < WIN) {
                    float4 v = make_float4(acc[mi][half*4], acc[mi][half*4+1],
                                           acc[mi][half*4+2], acc[mi][half*4+3]);
                    *(float4*)&qp[gm * WIN + gn] = v;
                }
            }
        }
    }
}

// ======== K4: 2 warps per example, fold K-split partials ================
__global__ void __launch_bounds__(256) k4_main(
        const int* __restrict__ e1i, const int* __restrict__ ri,
        const int* __restrict__ e2i, const float* __restrict__ Et,
        const float* __restrict__ bn0g, const float* __restrict__ bn0b,
        const float* __restrict__ bn0m, const float* __restrict__ bn0v,
        const float* __restrict__ bias, float* __restrict__ out) {
    __shared__ float part[8];
    int tid = threadIdx.x;
    int lane = tid & 31;
    int half = (tid >> 5) & 1;
    int k = tid >> 6;
    int b = blockIdx.x * 4 + k;
    float s0 = bn0g[0] * rsqrtf(bn0v[0] + EPSBN);
    float c0 = bn0b[0] - bn0m[0] * s0;
    int r  = ri[b];
    int e  = half ? e2i[b] : e1i[b];
    const float4* __restrict__ E  = (const float4*)(Et + (size_t)e * D1);
    const float4* __restrict__ Q0 = (const float4*)(g_qp + r * WIN) + half * 50;
    const float4* __restrict__ Q1 = (const float4*)(g_qp + NREL * WIN + r * WIN) + half * 50;
    float acc = half ? 0.f : g_c1[lane];
    {
        float4 ev = E[lane];
        float4 qa = Q0[lane], qb = Q1[lane];
        acc = fmaf(fmaf(s0, ev.x, c0), qa.x + qb.x, acc);
        acc = fmaf(fmaf(s0, ev.y, c0), qa.y + qb.y, acc);
        acc = fmaf(fmaf(s0, ev.z, c0), qa.z + qb.z, acc);
        acc = fmaf(fmaf(s0, ev.w, c0), qa.w + qb.w, acc);
    }
    if (lane < 18) {
        float4 ev = E[lane + 32];
        float4 qa = Q0[lane + 32], qb = Q1[lane + 32];
        acc = fmaf(fmaf(s0, ev.x, c0), qa.x + qb.x, acc);
        acc = fmaf(fmaf(s0, ev.y, c0), qa.y + qb.y, acc);
        acc = fmaf(fmaf(s0, ev.z, c0), qa.z + qb.z, acc);
        acc = fmaf(fmaf(s0, ev.w, c0), qa.w + qb.w, acc);
    }
    for (int o = 16; o; o >>= 1) acc += __shfl_down_sync(0xffffffffu, acc, o);
    if (lane == 0) part[tid >> 5] = acc;
    __syncthreads();
    if ((tid & 63) == 0) {
        int w = tid >> 5;
        float z = part[w] + part[w + 1] + g_scal0;
        out[b] = tanhf(z) + bias[0];
    }
}

// ---------------- launch ------------------------------------------------
extern "C" void kernel_launch(void* const* d_in, const int* in_sizes, int n_in,
                              void* d_out, int out_size) {
    const int*   e1_idx  = (const int*)  d_in[0];
    const int*   r_idx   = (const int*)  d_in[1];
    const int*   e2_idx  = (const int*)  d_in[2];
    const float* E_table = (const float*)d_in[3];
    const float* R_table = (const float*)d_in[4];
    const float* bn0g    = (const float*)d_in[5];
    const float* bn0b    = (const float*)d_in[6];
    const float* bn0m    = (const float*)d_in[7];
    const float* bn0v    = (const float*)d_in[8];
    const float* fc1w    = (const float*)d_in[9];
    const float* fc1b    = (const float*)d_in[10];
    const float* bn1g    = (const float*)d_in[11];
    const float* bn1b    = (const float*)d_in[12];
    const float* bn1m    = (const float*)d_in[13];
    const float* bn1v    = (const float*)d_in[14];
    const float* fcw     = (const float*)d_in[15];
    const float* fcb     = (const float*)d_in[16];
    const float* bn2g    = (const float*)d_in[17];
    const float* bn2b    = (const float*)d_in[18];
    const float* bn2m    = (const float*)d_in[19];
    const float* bn2v    = (const float*)d_in[20];
    const float* fc2w    = (const float*)d_in[21];
    const float* fc2b    = (const float*)d_in[22];
    const float* bias    = (const float*)d_in[23];
    float* out = (float*)d_out;

    k1_v<<<NSPLIT * FBLK, 256>>>(fcw, bn2g, bn2v, fc2w);
    gemm1_krel<<<dim3(G1_ROWB, G1_COLB), 256>>>(R_table, fc1w, fc1b);
    kv_build<<<OC + 1, 256>>>(bn1g, bn1b, bn1m, bn1v,
                              bn2g, bn2b, bn2m, bn2v, fc2w, fc2b, fcb);
    gemm2_q<<<dim3(8, 7, KSPL), 128>>>();
    k4_main<<<BATCH / 4, 256>>>(e1_idx, r_idx, e2_idx, E_table,
                                bn0g, bn0b, bn0m, bn0v, bias, out);
}

// round 6
// speedup vs baseline: 1.0960x; 1.0452x over previous
#include <cuda_runtime.h>
#include <cuda_bf16.h>
#include <math.h>

#define BATCH   4096
#define D1      200
#define NREL    500
#define NRELP   512
#define M1      288
#define OC      32
#define FW      9
#define WOUT    392
#define WIN     400
#define VPAD    512      // padded Vmat row stride (t-tile staging stays in-bounds)
#define FCLEN   12544
#define EPSBN   1e-5f
#define NSPLIT  8
#define ILEN    50
#define FBLK    49

#define G1_ROWB 16
#define G1_COLB 5

// gemm2 v4 geometry
#define RT      16       // rel tile
#define TT      128      // t tile
#define KSPL    4
#define KLEN    72       // 288/4
#define RTILES  32       // ceil(512/16)
#define TTILES  4        // ceil(512/128)

// ---------------- device scratch ----------------
__device__ float g_vp[NSPLIT * FCLEN];
__device__ float g_KrelT[M1 * NRELP];      // K-major [k][rel]; pad rels stay zero
__device__ float g_Vmat[M1 * VPAD];        // pad cols stay zero
__device__ float g_qp[KSPL * NREL * WIN];  // K-split partials
__device__ float g_q[NREL * WIN];
__device__ float g_c1[OC];
__device__ float g_scal0;

// ======== K1: v partials (8-way i-split) ================================
__global__ void __launch_bounds__(256) k1_v(
        const float* __restrict__ fcw,
        const float* __restrict__ bn2g, const float* __restrict__ bn2v,
        const float* __restrict__ fc2w) {
    __shared__ float sa[ILEN];
    int tid = threadIdx.x;
    int isp = blockIdx.x / FBLK, fb = blockIdx.x % FBLK;
    if (tid < ILEN) {
        int i = isp * ILEN + tid;
        float s2 = bn2g[i] * rsqrtf(bn2v[i] + EPSBN);
        sa[tid] = s2 * fc2w[i];
    }
    __syncthreads();
    int f = fb * 256 + tid;
    const float* __restrict__ p = fcw + (size_t)isp * ILEN * FCLEN + f;
    float acc = 0.f;
#pragma unroll
    for (int ii = 0; ii < ILEN; ii++)
        acc = fmaf(sa[ii], p[(size_t)ii * FCLEN], acc);
    g_vp[isp * FCLEN + f] = acc;
}

// ======== GEMM1: KrelT[k][rel] = (R @ fc1w^T + b)^T =====================
__global__ void __launch_bounds__(256) gemm1_krel(
        const float* __restrict__ R, const float* __restrict__ fc1w,
        const float* __restrict__ fc1b) {
    __shared__ float Bs[8 * 68];
    __shared__ float As[8 * 36];
    int tid = threadIdx.x;
    int row0 = blockIdx.x * 32, col0 = blockIdx.y * 64;
    int tx = tid & 15, ty = tid >> 4;
    float acc[2][4] = {};
    for (int k0 = 0; k0 < 200; k0 += 8) {
        {
            int m = tid >> 3, kk = tid & 7;
            int gm = row0 + m;
            As[kk * 36 + m] = (gm < NREL) ? R[gm * 200 + k0 + kk] : 0.f;
        }
#pragma unroll
        for (int l = 0; l < 2; l++) {
            int e = l * 256 + tid;
            int n = e >> 3, kk = e & 7;
            int gn = col0 + n;
            Bs[kk * 68 + n] = (gn < M1) ? fc1w[gn * 200 + k0 + kk] : 0.f;
        }
        __syncthreads();
#pragma unroll
        for (int kk = 0; kk < 8; kk++) {
            float a0 = As[kk * 36 + ty * 2];
            float a1 = As[kk * 36 + ty * 2 + 1];
            float4 b4 = *(const float4*)&Bs[kk * 68 + tx * 4];
            acc[0][0] = fmaf(a0, b4.x, acc[0][0]); acc[0][1] = fmaf(a0, b4.y, acc[0][1]);
            acc[0][2] = fmaf(a0, b4.z, acc[0][2]); acc[0][3] = fmaf(a0, b4.w, acc[0][3]);
            acc[1][0] = fmaf(a1, b4.x, acc[1][0]); acc[1][1] = fmaf(a1, b4.y, acc[1][1]);
            acc[1][2] = fmaf(a1, b4.z, acc[1][2]); acc[1][3] = fmaf(a1, b4.w, acc[1][3]);
        }
        __syncthreads();
    }
#pragma unroll
    for (int mi = 0; mi < 2; mi++) {
        int gm = row0 + ty * 2 + mi;
        if (gm < NREL) {
#pragma unroll
            for (int ni = 0; ni < 4; ni++) {
                int gn = col0 + tx * 4 + ni;
                if (gn < M1) g_KrelT[gn * NRELP + gm] = acc[mi][ni] + fc1b[gn];
            }
        }
    }
}

// ======== KV: fold partials, scale, shift-replicate (+ scal0 block) =====
__global__ void __launch_bounds__(256) kv_build(
        const float* __restrict__ bn1g, const float* __restrict__ bn1b,
        const float* __restrict__ bn1m, const float* __restrict__ bn1v,
        const float* __restrict__ bn2g, const float* __restrict__ bn2b,
        const float* __restrict__ bn2m, const float* __restrict__ bn2v,
        const float* __restrict__ fc2w, const float* __restrict__ fc2b,
        const float* __restrict__ fcb) {
    __shared__ float sv[WOUT];
    __shared__ float red[256];
    int tid = threadIdx.x;
    if (blockIdx.x == OC) {                // scal0
        float t = 0.f;
        for (int i = tid; i < WIN; i += 256) {
            float s2 = bn2g[i] * rsqrtf(bn2v[i] + EPSBN);
            float a  = s2 * fc2w[i];
            t += (bn2b[i] - bn2m[i] * s2) * fc2w[i] + a * fcb[i];
        }
        red[tid] = t;
        __syncthreads();
        for (int s = 128; s; s >>= 1) { if (tid < s) red[tid] += red[tid + s]; __syncthreads(); }
        if (tid == 0) g_scal0 = red[0] + fc2b[0];
        return;
    }
    int o = blockIdx.x;
    float inv1 = bn1g[o] * rsqrtf(bn1v[o] + EPSBN);
    float vsum = 0.f;
    for (int w = tid; w < WOUT; w += 256) {
        float s = 0.f;
#pragma unroll
        for (int sp = 0; sp < NSPLIT; sp++) s += g_vp[sp * FCLEN + o * WOUT + w];
        sv[w] = s * inv1;
        vsum += s;
    }
    red[tid] = vsum;
    __syncthreads();
    for (int s = 128; s; s >>= 1) { if (tid < s) red[tid] += red[tid + s]; __syncthreads(); }
    if (tid == 0) g_c1[o] = (bn1b[o] - bn1m[o] * inv1) * red[0];
    __syncthreads();
    for (int idx = tid; idx < FW * WIN; idx += 256) {
        int j = idx / WIN, t = idx - j * WIN;
        int w = t - j;
        g_Vmat[(o * FW + j) * VPAD + t] = ((unsigned)w < (unsigned)WOUT) ? sv[w] : 0.f;
    }
}

// ======== GEMM2 v4: smem-staged, 16rel x 128t x 72k, 512 blocks =========
__global__ void __launch_bounds__(128) gemm2_q() {
    __shared__ float  sV[KLEN][TT];
    __shared__ float4 sK[KLEN][RT / 4];
    int tid = threadIdx.x;
    int r0 = blockIdx.x * RT;
    int t0 = blockIdx.y * TT;
    int k0 = blockIdx.z * KLEN;

    // stage Vmat chunk: 72x128 floats = 2304 f4, 18 per thread, coalesced
    for (int i = tid; i < KLEN * (TT / 4); i += 128) {
        int kk = i / (TT / 4), c4 = i % (TT / 4);
        ((float4*)sV[kk])[c4] =
            *(const float4*)&g_Vmat[(size_t)(k0 + kk) * VPAD + t0 + c4 * 4];
    }
    // stage Krel chunk: 72x16 floats = 288 f4
    for (int i = tid; i < KLEN * (RT / 4); i += 128) {
        int kk = i / (RT / 4), r4 = i % (RT / 4);
        sK[kk][r4] = *(const float4*)&g_KrelT[(size_t)(k0 + kk) * NRELP + r0 + r4 * 4];
    }
    __syncthreads();

    int t = t0 + tid;
    float acc[RT] = {};
    if (t < WIN) {
#pragma unroll 4
        for (int kk = 0; kk < KLEN; kk++) {
            float vv = sV[kk][tid];
            float4 a = sK[kk][0], b = sK[kk][1], c = sK[kk][2], d = sK[kk][3];
            acc[0]  = fmaf(a.x, vv, acc[0]);  acc[1]  = fmaf(a.y, vv, acc[1]);
            acc[2]  = fmaf(a.z, vv, acc[2]);  acc[3]  = fmaf(a.w, vv, acc[3]);
            acc[4]  = fmaf(b.x, vv, acc[4]);  acc[5]  = fmaf(b.y, vv, acc[5]);
            acc[6]  = fmaf(b.z, vv, acc[6]);  acc[7]  = fmaf(b.w, vv, acc[7]);
            acc[8]  = fmaf(c.x, vv, acc[8]);  acc[9]  = fmaf(c.y, vv, acc[9]);
            acc[10] = fmaf(c.z, vv, acc[10]); acc[11] = fmaf(c.w, vv, acc[11]);
            acc[12] = fmaf(d.x, vv, acc[12]); acc[13] = fmaf(d.y, vv, acc[13]);
            acc[14] = fmaf(d.z, vv, acc[14]); acc[15] = fmaf(d.w, vv, acc[15]);
        }
        float* __restrict__ qp = g_qp + (size_t)blockIdx.z * (NREL * WIN);
#pragma unroll
        for (int rr = 0; rr < RT; rr++) {
            int r = r0 + rr;
            if (r < NREL) qp[r * WIN + t] = acc[rr];   // coalesced over t
        }
    }
}

// ======== FOLD: q = sum of 4 K-split partials ===========================
__global__ void __launch_bounds__(256) fold_q() {
    int idx = blockIdx.x * 256 + threadIdx.x;       // f4 index
    if (idx >= NREL * WIN / 4) return;
    const float4* p0 = (const float4*)g_qp;
    const float4* p1 = (const float4*)(g_qp + 1 * NREL * WIN);
    const float4* p2 = (const float4*)(g_qp + 2 * NREL * WIN);
    const float4* p3 = (const float4*)(g_qp + 3 * NREL * WIN);
    float4 a = p0[idx], b = p1[idx], c = p2[idx], d = p3[idx];
    float4 s = make_float4(a.x + b.x + c.x + d.x, a.y + b.y + c.y + d.y,
                           a.z + b.z + c.z + d.z, a.w + b.w + c.w + d.w);
    ((float4*)g_q)[idx] = s;
}

// ======== K4: 2 warps per example ======================================
__global__ void __launch_bounds__(256) k4_main(
        const int* __restrict__ e1i, const int* __restrict__ ri,
        const int* __restrict__ e2i, const float* __restrict__ Et,
        const float* __restrict__ bn0g, const float* __restrict__ bn0b,
        const float* __restrict__ bn0m, const float* __restrict__ bn0v,
        const float* __restrict__ bias, float* __restrict__ out) {
    __shared__ float part[8];
    int tid = threadIdx.x;
    int lane = tid & 31;
    int half = (tid >> 5) & 1;
    int k = tid >> 6;
    int b = blockIdx.x * 4 + k;
    float s0 = bn0g[0] * rsqrtf(bn0v[0] + EPSBN);
    float c0 = bn0b[0] - bn0m[0] * s0;
    int r  = ri[b];
    int e  = half ? e2i[b] : e1i[b];
    const float4* __restrict__ E = (const float4*)(Et + (size_t)e * D1);
    const float4* __restrict__ Q = (const float4*)(g_q + r * WIN) + half * 50;
    float acc = half ? 0.f : g_c1[lane];
    {
        float4 ev = E[lane], qv = Q[lane];
        acc = fmaf(fmaf(s0, ev.x, c0), qv.x, acc);
        acc = fmaf(fmaf(s0, ev.y, c0), qv.y, acc);
        acc = fmaf(fmaf(s0, ev.z, c0), qv.z, acc);
        acc = fmaf(fmaf(s0, ev.w, c0), qv.w, acc);
    }
    if (lane < 18) {
        float4 ev = E[lane + 32], qv = Q[lane + 32];
        acc = fmaf(fmaf(s0, ev.x, c0), qv.x, acc);
        acc = fmaf(fmaf(s0, ev.y, c0), qv.y, acc);
        acc = fmaf(fmaf(s0, ev.z, c0), qv.z, acc);
        acc = fmaf(fmaf(s0, ev.w, c0), qv.w, acc);
    }
    for (int o = 16; o; o >>= 1) acc += __shfl_down_sync(0xffffffffu, acc, o);
    if (lane == 0) part[tid >> 5] = acc;
    __syncthreads();
    if ((tid & 63) == 0) {
        int w = tid >> 5;
        float z = part[w] + part[w + 1] + g_scal0;
        out[b] = tanhf(z) + bias[0];
    }
}

// ---------------- launch ------------------------------------------------
extern "C" void kernel_launch(void* const* d_in, const int* in_sizes, int n_in,
                              void* d_out, int out_size) {
    const int*   e1_idx  = (const int*)  d_in[0];
    const int*   r_idx   = (const int*)  d_in[1];
    const int*   e2_idx  = (const int*)  d_in[2];
    const float* E_table = (const float*)d_in[3];
    const float* R_table = (const float*)d_in[4];
    const float* bn0g    = (const float*)d_in[5];
    const float* bn0b    = (const float*)d_in[6];
    const float* bn0m    = (const float*)d_in[7];
    const float* bn0v    = (const float*)d_in[8];
    const float* fc1w    = (const float*)d_in[9];
    const float* fc1b    = (const float*)d_in[10];
    const float* bn1g    = (const float*)d_in[11];
    const float* bn1b    = (const float*)d_in[12];
    const float* bn1m    = (const float*)d_in[13];
    const float* bn1v    = (const float*)d_in[14];
    const float* fcw     = (const float*)d_in[15];
    const float* fcb     = (const float*)d_in[16];
    const float* bn2g    = (const float*)d_in[17];
    const float* bn2b    = (const float*)d_in[18];
    const float* bn2m    = (const float*)d_in[19];
    const float* bn2v    = (const float*)d_in[20];
    const float* fc2w    = (const float*)d_in[21];
    const float* fc2b    = (const float*)d_in[22];
    const float* bias    = (const float*)d_in[23];
    float* out = (float*)d_out;

    k1_v<<<NSPLIT * FBLK, 256>>>(fcw, bn2g, bn2v, fc2w);
    gemm1_krel<<<dim3(G1_ROWB, G1_COLB), 256>>>(R_table, fc1w, fc1b);
    kv_build<<<OC + 1, 256>>>(bn1g, bn1b, bn1m, bn1v,
                              bn2g, bn2b, bn2m, bn2v, fc2w, fc2b, fcb);
    gemm2_q<<<dim3(RTILES, TTILES, KSPL), 128>>>();
    fold_q<<<(NREL * WIN / 4 + 255) / 256, 256>>>();
    k4_main<<<BATCH / 4, 256>>>(e1_idx, r_idx, e2_idx, E_table,
                                bn0g, bn0b, bn0m, bn0v, bias, out);
}

// round 7
// speedup vs baseline: 1.2312x; 1.1233x over previous
#include <cuda_runtime.h>
#include <cuda_bf16.h>
#include <math.h>

#define BATCH   4096
#define D1      200
#define NREL    500
#define NRELP   512
#define M1      288
#define OC      32
#define FW      9
#define WOUT    392
#define WIN     400
#define VPAD    512
#define FCLEN   12544
#define EPSBN   1e-5f
#define NSPLIT  8
#define ILEN    50
#define FBLK    49

#define G1_ROWB 16
#define G1_COLB 5

// gemm2 v5 geometry
#define RT      32       // rel tile
#define TT      64       // t tile
#define KSPL    6
#define KLEN    48       // 288/6
#define RTILES  16       // 512/32
#define TTILES  7        // ceil(400/64)

// ---------------- device scratch ----------------
__device__ float g_vp[NSPLIT * FCLEN];
__device__ float g_KrelT[M1 * NRELP];      // K-major [k][rel]; pad rels stay zero
__device__ float g_Vmat[M1 * VPAD];        // pad cols stay zero
__device__ float g_qp[KSPL * NREL * WIN];  // K-split partials
__device__ float g_c1[OC];
__device__ float g_scal0;

// ======== K1: v partials (8-way i-split) ================================
__global__ void __launch_bounds__(256) k1_v(
        const float* __restrict__ fcw,
        const float* __restrict__ bn2g, const float* __restrict__ bn2v,
        const float* __restrict__ fc2w) {
    __shared__ float sa[ILEN];
    int tid = threadIdx.x;
    int isp = blockIdx.x / FBLK, fb = blockIdx.x % FBLK;
    if (tid < ILEN) {
        int i = isp * ILEN + tid;
        float s2 = bn2g[i] * rsqrtf(bn2v[i] + EPSBN);
        sa[tid] = s2 * fc2w[i];
    }
    __syncthreads();
    int f = fb * 256 + tid;
    const float* __restrict__ p = fcw + (size_t)isp * ILEN * FCLEN + f;
    float acc = 0.f;
#pragma unroll
    for (int ii = 0; ii < ILEN; ii++)
        acc = fmaf(sa[ii], p[(size_t)ii * FCLEN], acc);
    g_vp[isp * FCLEN + f] = acc;
}

// ======== GEMM1: KrelT[k][rel] = (R @ fc1w^T + b)^T =====================
__global__ void __launch_bounds__(256) gemm1_krel(
        const float* __restrict__ R, const float* __restrict__ fc1w,
        const float* __restrict__ fc1b) {
    __shared__ float Bs[8 * 68];
    __shared__ float As[8 * 36];
    int tid = threadIdx.x;
    int row0 = blockIdx.x * 32, col0 = blockIdx.y * 64;
    int tx = tid & 15, ty = tid >> 4;
    float acc[2][4] = {};
    for (int k0 = 0; k0 < 200; k0 += 8) {
        {
            int m = tid >> 3, kk = tid & 7;
            int gm = row0 + m;
            As[kk * 36 + m] = (gm < NREL) ? R[gm * 200 + k0 + kk] : 0.f;
        }
#pragma unroll
        for (int l = 0; l < 2; l++) {
            int e = l * 256 + tid;
            int n = e >> 3, kk = e & 7;
            int gn = col0 + n;
            Bs[kk * 68 + n] = (gn < M1) ? fc1w[gn * 200 + k0 + kk] : 0.f;
        }
        __syncthreads();
#pragma unroll
        for (int kk = 0; kk < 8; kk++) {
            float a0 = As[kk * 36 + ty * 2];
            float a1 = As[kk * 36 + ty * 2 + 1];
            float4 b4 = *(const float4*)&Bs[kk * 68 + tx * 4];
            acc[0][0] = fmaf(a0, b4.x, acc[0][0]); acc[0][1] = fmaf(a0, b4.y, acc[0][1]);
            acc[0][2] = fmaf(a0, b4.z, acc[0][2]); acc[0][3] = fmaf(a0, b4.w, acc[0][3]);
            acc[1][0] = fmaf(a1, b4.x, acc[1][0]); acc[1][1] = fmaf(a1, b4.y, acc[1][1]);
            acc[1][2] = fmaf(a1, b4.z, acc[1][2]); acc[1][3] = fmaf(a1, b4.w, acc[1][3]);
        }
        __syncthreads();
    }
#pragma unroll
    for (int mi = 0; mi < 2; mi++) {
        int gm = row0 + ty * 2 + mi;
        if (gm < NREL) {
#pragma unroll
            for (int ni = 0; ni < 4; ni++) {
                int gn = col0 + tx * 4 + ni;
                if (gn < M1) g_KrelT[gn * NRELP + gm] = acc[mi][ni] + fc1b[gn];
            }
        }
    }
}

// ======== KV: fold partials, scale, shift-replicate (+ scal0 block) =====
__global__ void __launch_bounds__(256) kv_build(
        const float* __restrict__ bn1g, const float* __restrict__ bn1b,
        const float* __restrict__ bn1m, const float* __restrict__ bn1v,
        const float* __restrict__ bn2g, const float* __restrict__ bn2b,
        const float* __restrict__ bn2m, const float* __restrict__ bn2v,
        const float* __restrict__ fc2w, const float* __restrict__ fc2b,
        const float* __restrict__ fcb) {
    __shared__ float sv[WOUT];
    __shared__ float red[256];
    int tid = threadIdx.x;
    if (blockIdx.x == OC) {                // scal0
        float t = 0.f;
        for (int i = tid; i < WIN; i += 256) {
            float s2 = bn2g[i] * rsqrtf(bn2v[i] + EPSBN);
            float a  = s2 * fc2w[i];
            t += (bn2b[i] - bn2m[i] * s2) * fc2w[i] + a * fcb[i];
        }
        red[tid] = t;
        __syncthreads();
        for (int s = 128; s; s >>= 1) { if (tid < s) red[tid] += red[tid + s]; __syncthreads(); }
        if (tid == 0) g_scal0 = red[0] + fc2b[0];
        return;
    }
    int o = blockIdx.x;
    float inv1 = bn1g[o] * rsqrtf(bn1v[o] + EPSBN);
    float vsum = 0.f;
    for (int w = tid; w < WOUT; w += 256) {
        float s = 0.f;
#pragma unroll
        for (int sp = 0; sp < NSPLIT; sp++) s += g_vp[sp * FCLEN + o * WOUT + w];
        sv[w] = s * inv1;
        vsum += s;
    }
    red[tid] = vsum;
    __syncthreads();
    for (int s = 128; s; s >>= 1) { if (tid < s) red[tid] += red[tid + s]; __syncthreads(); }
    if (tid == 0) g_c1[o] = (bn1b[o] - bn1m[o] * inv1) * red[0];
    __syncthreads();
    for (int idx = tid; idx < FW * WIN; idx += 256) {
        int j = idx / WIN, t = idx - j * WIN;
        int w = t - j;
        g_Vmat[(o * FW + j) * VPAD + t] = ((unsigned)w < (unsigned)WOUT) ? sv[w] : 0.f;
    }
}

// ======== GEMM2 v5: 32rel x 64t x 48k, 4x4 reg tile, 672 blocks =========
__global__ void __launch_bounds__(128) gemm2_q() {
    __shared__ float sK[KLEN][RT];         // [kk][rel]
    __shared__ float sV[KLEN][TT];         // [kk][t]
    int tid = threadIdx.x;
    int tx = tid & 15;                     // t group  (x4)
    int ty = tid >> 4;                     // rel group (x4), 0..7
    int r0 = blockIdx.x * RT;
    int t0 = blockIdx.y * TT;
    int k0 = blockIdx.z * KLEN;

    // stage Krel chunk: 48x32 = 384 f4
    for (int i = tid; i < KLEN * (RT / 4); i += 128) {
        int kk = i >> 3, c = i & 7;
        *(float4*)&sK[kk][c * 4] =
            *(const float4*)&g_KrelT[(size_t)(k0 + kk) * NRELP + r0 + c * 4];
    }
    // stage Vmat chunk: 48x64 = 768 f4
    for (int i = tid; i < KLEN * (TT / 4); i += 128) {
        int kk = i >> 4, c = i & 15;
        *(float4*)&sV[kk][c * 4] =
            *(const float4*)&g_Vmat[(size_t)(k0 + kk) * VPAD + t0 + c * 4];
    }
    __syncthreads();

    float acc[4][4] = {};
#pragma unroll 8
    for (int kk = 0; kk < KLEN; kk++) {
        float4 a4 = *(const float4*)&sK[kk][ty * 4];
        float4 b4 = *(const float4*)&sV[kk][tx * 4];
        acc[0][0] = fmaf(a4.x, b4.x, acc[0][0]); acc[0][1] = fmaf(a4.x, b4.y, acc[0][1]);
        acc[0][2] = fmaf(a4.x, b4.z, acc[0][2]); acc[0][3] = fmaf(a4.x, b4.w, acc[0][3]);
        acc[1][0] = fmaf(a4.y, b4.x, acc[1][0]); acc[1][1] = fmaf(a4.y, b4.y, acc[1][1]);
        acc[1][2] = fmaf(a4.y, b4.z, acc[1][2]); acc[1][3] = fmaf(a4.y, b4.w, acc[1][3]);
        acc[2][0] = fmaf(a4.z, b4.x, acc[2][0]); acc[2][1] = fmaf(a4.z, b4.y, acc[2][1]);
        acc[2][2] = fmaf(a4.z, b4.z, acc[2][2]); acc[2][3] = fmaf(a4.z, b4.w, acc[2][3]);
        acc[3][0] = fmaf(a4.w, b4.x, acc[3][0]); acc[3][1] = fmaf(a4.w, b4.y, acc[3][1]);
        acc[3][2] = fmaf(a4.w, b4.z, acc[3][2]); acc[3][3] = fmaf(a4.w, b4.w, acc[3][3]);
    }

    float* __restrict__ qp = g_qp + (size_t)blockIdx.z * (NREL * WIN);
    int gn = t0 + tx * 4;
    if (gn < WIN) {
#pragma unroll
        for (int mi = 0; mi < 4; mi++) {
            int gm = r0 + ty * 4 + mi;
            if (gm < NREL) {
                float4 v = make_float4(acc[mi][0], acc[mi][1], acc[mi][2], acc[mi][3]);
                *(float4*)&qp[gm * WIN + gn] = v;
            }
        }
    }
}

// ======== K4: 2 warps per example, fold the 6 K-split partials ==========
__global__ void __launch_bounds__(256) k4_main(
        const int* __restrict__ e1i, const int* __restrict__ ri,
        const int* __restrict__ e2i, const float* __restrict__ Et,
        const float* __restrict__ bn0g, const float* __restrict__ bn0b,
        const float* __restrict__ bn0m, const float* __restrict__ bn0v,
        const float* __restrict__ bias, float* __restrict__ out) {
    __shared__ float part[8];
    int tid = threadIdx.x;
    int lane = tid & 31;
    int half = (tid >> 5) & 1;
    int k = tid >> 6;
    int b = blockIdx.x * 4 + k;
    float s0 = bn0g[0] * rsqrtf(bn0v[0] + EPSBN);
    float c0 = bn0b[0] - bn0m[0] * s0;
    int r  = ri[b];
    int e  = half ? e2i[b] : e1i[b];
    const float4* __restrict__ E = (const float4*)(Et + (size_t)e * D1);
    const float* __restrict__ qbase = g_qp + (size_t)r * WIN;
    float acc = half ? 0.f : g_c1[lane];
    {
        int idx = lane + half * 50;
        float4 ev = E[lane];
        float4 qs = make_float4(0.f, 0.f, 0.f, 0.f);
#pragma unroll
        for (int p = 0; p < KSPL; p++) {
            float4 t = ((const float4*)(qbase + (size_t)p * (NREL * WIN)))[idx];
            qs.x += t.x; qs.y += t.y; qs.z += t.z; qs.w += t.w;
        }
        acc = fmaf(fmaf(s0, ev.x, c0), qs.x, acc);
        acc = fmaf(fmaf(s0, ev.y, c0), qs.y, acc);
        acc = fmaf(fmaf(s0, ev.z, c0), qs.z, acc);
        acc = fmaf(fmaf(s0, ev.w, c0), qs.w, acc);
    }
    if (lane < 18) {
        int idx = lane + 32 + half * 50;
        float4 ev = E[lane + 32];
        float4 qs = make_float4(0.f, 0.f, 0.f, 0.f);
#pragma unroll
        for (int p = 0; p < KSPL; p++) {
            float4 t = ((const float4*)(qbase + (size_t)p * (NREL * WIN)))[idx];
            qs.x += t.x; qs.y += t.y; qs.z += t.z; qs.w += t.w;
        }
        acc = fmaf(fmaf(s0, ev.x, c0), qs.x, acc);
        acc = fmaf(fmaf(s0, ev.y, c0), qs.y, acc);
        acc = fmaf(fmaf(s0, ev.z, c0), qs.z, acc);
        acc = fmaf(fmaf(s0, ev.w, c0), qs.w, acc);
    }
    for (int o = 16; o; o >>= 1) acc += __shfl_down_sync(0xffffffffu, acc, o);
    if (lane == 0) part[tid >> 5] = acc;
    __syncthreads();
    if ((tid & 63) == 0) {
        int w = tid >> 5;
        float z = part[w] + part[w + 1] + g_scal0;
        out[b] = tanhf(z) + bias[0];
    }
}

// ---------------- launch ------------------------------------------------
extern "C" void kernel_launch(void* const* d_in, const int* in_sizes, int n_in,
                              void* d_out, int out_size) {
    const int*   e1_idx  = (const int*)  d_in[0];
    const int*   r_idx   = (const int*)  d_in[1];
    const int*   e2_idx  = (const int*)  d_in[2];
    const float* E_table = (const float*)d_in[3];
    const float* R_table = (const float*)d_in[4];
    const float* bn0g    = (const float*)d_in[5];
    const float* bn0b    = (const float*)d_in[6];
    const float* bn0m    = (const float*)d_in[7];
    const float* bn0v    = (const float*)d_in[8];
    const float* fc1w    = (const float*)d_in[9];
    const float* fc1b    = (const float*)d_in[10];
    const float* bn1g    = (const float*)d_in[11];
    const float* bn1b    = (const float*)d_in[12];
    const float* bn1m    = (const float*)d_in[13];
    const float* bn1v    = (const float*)d_in[14];
    const float* fcw     = (const float*)d_in[15];
    const float* fcb     = (const float*)d_in[16];
    const float* bn2g    = (const float*)d_in[17];
    const float* bn2b    = (const float*)d_in[18];
    const float* bn2m    = (const float*)d_in[19];
    const float* bn2v    = (const float*)d_in[20];
    const float* fc2w    = (const float*)d_in[21];
    const float* fc2b    = (const float*)d_in[22];
    const float* bias    = (const float*)d_in[23];
    float* out = (float*)d_out;

    k1_v<<<NSPLIT * FBLK, 256>>>(fcw, bn2g, bn2v, fc2w);
    gemm1_krel<<<dim3(G1_ROWB, G1_COLB), 256>>>(R_table, fc1w, fc1b);
    kv_build<<<OC + 1, 256>>>(bn1g, bn1b, bn1m, bn1v,
                              bn2g, bn2b, bn2m, bn2v, fc2w, fc2b, fcb);
    gemm2_q<<<dim3(RTILES, TTILES, KSPL), 128>>>();
    k4_main<<<BATCH / 4, 256>>>(e1_idx, r_idx, e2_idx, E_table,
                                bn0g, bn0b, bn0m, bn0v, bias, out);
}